// round 17
// baseline (speedup 1.0000x reference)
#include <cuda_runtime.h>
#include <cuda_fp16.h>
#include <cuda_bf16.h>
#include <math.h>
#include <stdint.h>

#define NPTS 20000
#define MPAD 20096              // 157 * 128
#define KNBR 16
#define MEDG (NPTS * KNBR)
#define CDIM 384
#define HEADS 6
#define QKVW 1152
#define SCALE 0.125f

#define ATTN_BX 74              // 74*6 = 444 CTAs = single wave at 3 CTA/SM
#define ATTN_NPB ((NPTS + ATTN_BX - 1) / ATTN_BX)   // 271

// ---------------- scratch (static device globals; no runtime alloc) ----------------
__device__ float g_q[NPTS * CDIM];              // q part, fp32 [N][384]
__device__ uint2 g_kvh2[NPTS * 768 / 4];        // k|v as fp16 [N][768] (k:0..383, v:384..767)
__device__ float g_sph[NPTS * 3];
__device__ int   g_rc[MEDG];
__device__ int   g_rs[MEDG];
// bf16 split operands (uint4-typed for guaranteed 16B alignment)
__device__ uint4 g_ahi4[MPAD * CDIM / 8];
__device__ uint4 g_alo4[MPAD * CDIM / 8];
__device__ uint4 g_xhi4[MPAD * CDIM / 8];       // attn output hi (pad rows stay 0)
__device__ uint4 g_xlo4[MPAD * CDIM / 8];
__device__ uint4 g_wqh4[QKVW * CDIM / 8];       // W_qkv^T hi  [1152][384]
__device__ uint4 g_wql4[QKVW * CDIM / 8];
__device__ uint4 g_wph4[CDIM * CDIM / 8];       // W_proj^T hi [384][384]
__device__ uint4 g_wpl4[CDIM * CDIM / 8];

// ================= helpers =================
__device__ __forceinline__ uint32_t smem_to_u32(const void* p) {
    uint32_t a;
    asm("{ .reg .u64 t; cvta.to.shared.u64 t, %1; cvt.u32.u64 %0, t; }" : "=r"(a) : "l"(p));
    return a;
}
__device__ __forceinline__ void cp_async16(uint32_t dst, const void* src) {
    asm volatile("cp.async.cg.shared.global [%0], [%1], 16;" :: "r"(dst), "l"(src) : "memory");
}
__device__ __forceinline__ void ldsm_x4(uint32_t* r, uint32_t addr) {
    asm volatile("ldmatrix.sync.aligned.m8n8.x4.shared.b16 {%0,%1,%2,%3}, [%4];"
                 : "=r"(r[0]), "=r"(r[1]), "=r"(r[2]), "=r"(r[3]) : "r"(addr));
}
__device__ __forceinline__ void mma_bf16(float* c, const uint32_t* a, const uint32_t* b) {
    asm volatile("mma.sync.aligned.m16n8k16.row.col.f32.bf16.bf16.f32 "
                 "{%0,%1,%2,%3},{%4,%5,%6,%7},{%8,%9},{%0,%1,%2,%3};"
                 : "+f"(c[0]), "+f"(c[1]), "+f"(c[2]), "+f"(c[3])
                 : "r"(a[0]), "r"(a[1]), "r"(a[2]), "r"(a[3]), "r"(b[0]), "r"(b[1]));
}

// ================= sphere coords =================
__global__ void sphere_kernel(const float* __restrict__ xyz) {
    int i = blockIdx.x * blockDim.x + threadIdx.x;
    if (i >= NPTS) return;
    float x = xyz[3 * i], y = xyz[3 * i + 1], z = xyz[3 * i + 2];
    const float R2D = 57.29577951308232f;
    g_sph[3 * i]     = (atan2f(y, x) + 3.14159265358979323846f) * R2D;
    g_sph[3 * i + 1] = atan2f(sqrtf(x * x + y * y), z) * R2D;
    g_sph[3 * i + 2] = sqrtf(x * x + y * y + z * z);
}

// ================= per-edge rel-index binning =================
__global__ void prep_kernel(const float* __restrict__ xyz,
                            const int* __restrict__ i0c, const int* __restrict__ i1c,
                            const int* __restrict__ i0s, const int* __restrict__ i1s) {
    int e = blockIdx.x * blockDim.x + threadIdx.x;
    if (e >= MEDG) return;
    {
        int a = i0c[e], b = i1c[e];
        int packed = 0;
#pragma unroll
        for (int d = 0; d < 3; d++) {
            float rel = xyz[3 * a + d] - xyz[3 * b + d];
            int idx = (int)floorf(rel / 0.25f) + 23;
            idx = min(max(idx, 0), 46);
            packed |= idx << (8 * d);
        }
        g_rc[e] = packed;
    }
    {
        int a = i0s[e], b = i1s[e];
        float r0 = g_sph[3 * a]     - g_sph[3 * b];
        float r1 = g_sph[3 * a + 1] - g_sph[3 * b + 1];
        float r2 = g_sph[3 * a + 2] - g_sph[3 * b + 2];
        int id0 = min(max((int)floorf(r0 / 5.0f) + 24, 0), 47);
        int id1 = min(max((int)floorf(r1 / 5.0f) + 24, 0), 47);
        const float A_ = 0.0125f;
        float ra = fabsf(r2);
        float flag = (r2 >= 0.0f) ? 1.0f : 0.0f;
        float idx = 2.0f * floorf(logf((ra + 2.0f * A_) / A_) / 0.6931471805599453f) - 2.0f;
        float check = (3.0f * exp2f(floorf(idx * 0.5f)) - 2.0f) * A_;
        idx += (check <= ra) ? 1.0f : 0.0f;
        idx = idx * (2.0f * flag - 1.0f) + (flag - 1.0f);
        int id2 = min(max((int)idx + 24, 0), 47);
        g_rs[e] = id0 | (id1 << 8) | (id2 << 16);
    }
}

// ================= bf16 split conversions =================
__global__ void conv_split_kernel(const float* __restrict__ src, uint2* __restrict__ hi,
                                  uint2* __restrict__ lo, int rows, int rowsPad) {
    int idx = blockIdx.x * blockDim.x + threadIdx.x;   // float4 index
    if (idx >= rowsPad * CDIM / 4) return;
    int row = (idx * 4) / CDIM;
    float4 v = (row < rows) ? __ldg((const float4*)src + idx)
                            : make_float4(0.f, 0.f, 0.f, 0.f);
    __nv_bfloat16 h0 = __float2bfloat16(v.x), h1 = __float2bfloat16(v.y);
    __nv_bfloat16 h2 = __float2bfloat16(v.z), h3 = __float2bfloat16(v.w);
    __nv_bfloat162 hA, hB, lA, lB;
    hA.x = h0; hA.y = h1; hB.x = h2; hB.y = h3;
    lA.x = __float2bfloat16(v.x - __bfloat162float(h0));
    lA.y = __float2bfloat16(v.y - __bfloat162float(h1));
    lB.x = __float2bfloat16(v.z - __bfloat162float(h2));
    lB.y = __float2bfloat16(v.w - __bfloat162float(h3));
    uint2 hu, lu;
    hu.x = *(uint32_t*)&hA; hu.y = *(uint32_t*)&hB;
    lu.x = *(uint32_t*)&lA; lu.y = *(uint32_t*)&lB;
    hi[idx] = hu;
    lo[idx] = lu;
}
// W [K=384][Nn] -> Wt hi/lo [Nn][384] via smem tiled transpose
__global__ void conv_wt_kernel(const float* __restrict__ W, __nv_bfloat16* __restrict__ hi,
                               __nv_bfloat16* __restrict__ lo, int Nn) {
    __shared__ float tile[32][33];
    int n0 = blockIdx.x * 32, k0 = blockIdx.y * 32;
    int tx = threadIdx.x, ty = threadIdx.y;   // block (32, 8)
#pragma unroll
    for (int i = ty; i < 32; i += 8)
        tile[i][tx] = __ldg(W + (size_t)(k0 + i) * Nn + n0 + tx);
    __syncthreads();
#pragma unroll
    for (int i = ty; i < 32; i += 8) {
        float v = tile[tx][i];                 // W[k0+tx][n0+i]
        __nv_bfloat16 h = __float2bfloat16(v);
        size_t o = (size_t)(n0 + i) * CDIM + k0 + tx;
        hi[o] = h;
        lo[o] = __float2bfloat16(v - __bfloat162float(h));
    }
}

// ================= mma.sync 3xBF16 GEMM (3-stage cp.async, 2 CTA/SM) ================
#define GBK 32
#define TILEB (128 * 64)             // 8192 bytes
#define BUFB (4 * TILEB)             // 32768: Ahi, Alo, Bhi, Blo
#define NSTAGE 3
#define NCHUNK (CDIM / GBK)          // 12

__global__ __launch_bounds__(256, 2)
void gemm_mma(const __nv_bfloat16* __restrict__ Ahi, const __nv_bfloat16* __restrict__ Alo,
              const __nv_bfloat16* __restrict__ Bhi, const __nv_bfloat16* __restrict__ Blo,
              const float* __restrict__ bias, float* __restrict__ Cf, __half* __restrict__ Ch,
              int M) {
    extern __shared__ __align__(128) char sm[];
    uint32_t sbase = smem_to_u32(sm);
    int tid = threadIdx.x;
    int warp = tid >> 5, lane = tid & 31;
    int g = lane >> 2, tg = lane & 3;
    int wm = warp >> 2, wn = warp & 3;       // 2 x 4 warps
    int bm = blockIdx.y * 128, bn = blockIdx.x * 128;

    float acc[4][4][4];
#pragma unroll
    for (int im = 0; im < 4; im++)
#pragma unroll
        for (int in = 0; in < 4; in++)
#pragma unroll
            for (int r = 0; r < 4; r++) acc[im][in][r] = 0.0f;

    int sub = lane >> 3;
    uint32_t offA[4][2];
#pragma unroll
    for (int im = 0; im < 4; im++) {
        int row = wm * 64 + im * 16 + (sub & 1) * 8 + (lane & 7);
        int sw = (row >> 1) & 3;
        int v = (sub >> 1) ^ sw;
#pragma unroll
        for (int ks = 0; ks < 2; ks++)
            offA[im][ks] = (uint32_t)(row * 64 + (((ks * 2) ^ v) * 16));
    }
    uint32_t offB[2][2];
#pragma unroll
    for (int p = 0; p < 2; p++) {
        int row = wn * 32 + p * 16 + (sub >> 1) * 8 + (lane & 7);
        int sw = (row >> 1) & 3;
        int v = (sub & 1) ^ sw;
#pragma unroll
        for (int ks = 0; ks < 2; ks++)
            offB[p][ks] = (uint32_t)(row * 64 + (((ks * 2) ^ v) * 16));
    }

    auto issue = [&](int c) {
        int kb = c * GBK;
        uint32_t dbase = sbase + (c % NSTAGE) * BUFB;
#pragma unroll
        for (int i = 0; i < 8; i++) {
            int t4 = i >> 1;
            int w = tid + (i & 1) * 256;
            int row = w >> 2, c4 = w & 3;
            const __nv_bfloat16* gp;
            if (t4 < 2) {
                size_t off = (size_t)(bm + row) * CDIM + kb + c4 * 8;
                gp = (t4 == 0 ? Ahi : Alo) + off;
            } else {
                size_t off = (size_t)(bn + row) * CDIM + kb + c4 * 8;
                gp = (t4 == 2 ? Bhi : Blo) + off;
            }
            uint32_t sts = (uint32_t)(row * 64 + ((c4 ^ ((row >> 1) & 3)) * 16));
            cp_async16(dbase + t4 * TILEB + sts, gp);
        }
        asm volatile("cp.async.commit_group;" ::: "memory");
    };

    issue(0);
    issue(1);
#pragma unroll 1
    for (int c = 0; c < NCHUNK; c++) {
        if (c == NCHUNK - 1) asm volatile("cp.async.wait_group 0;" ::: "memory");
        else                 asm volatile("cp.async.wait_group 1;" ::: "memory");
        __syncthreads();
        if (c + 2 < NCHUNK) issue(c + 2);

        uint32_t tb = sbase + (c % NSTAGE) * BUFB;
#pragma unroll
        for (int ks = 0; ks < 2; ks++) {
            uint32_t ah[4][4], al[4][4];
#pragma unroll
            for (int im = 0; im < 4; im++) {
                ldsm_x4(ah[im], tb + 0 * TILEB + offA[im][ks]);
                ldsm_x4(al[im], tb + 1 * TILEB + offA[im][ks]);
            }
            uint32_t bh[4][2], bl[4][2];
#pragma unroll
            for (int p = 0; p < 2; p++) {
                uint32_t r4[4];
                ldsm_x4(r4, tb + 2 * TILEB + offB[p][ks]);
                bh[2 * p][0] = r4[0]; bh[2 * p][1] = r4[1];
                bh[2 * p + 1][0] = r4[2]; bh[2 * p + 1][1] = r4[3];
                ldsm_x4(r4, tb + 3 * TILEB + offB[p][ks]);
                bl[2 * p][0] = r4[0]; bl[2 * p][1] = r4[1];
                bl[2 * p + 1][0] = r4[2]; bl[2 * p + 1][1] = r4[3];
            }
#pragma unroll
            for (int im = 0; im < 4; im++)
#pragma unroll
                for (int in = 0; in < 4; in++) {
                    mma_bf16(acc[im][in], ah[im], bh[in]);
                    mma_bf16(acc[im][in], ah[im], bl[in]);
                    mma_bf16(acc[im][in], al[im], bh[in]);
                }
        }
        __syncthreads();
    }

    // ---- epilogue ----
    if (Ch != nullptr && bn >= 384) {
#pragma unroll
        for (int in = 0; in < 4; in++) {
            int col = bn + wn * 32 + in * 8 + 2 * tg;
            float b0 = __ldg(bias + col), b1 = __ldg(bias + col + 1);
            int ck = col - 384;
#pragma unroll
            for (int im = 0; im < 4; im++) {
                int row0 = bm + wm * 64 + im * 16 + g;
                if (row0 < M)
                    *(__half2*)(Ch + (size_t)row0 * 768 + ck) =
                        __floats2half2_rn(acc[im][in][0] + b0, acc[im][in][1] + b1);
                if (row0 + 8 < M)
                    *(__half2*)(Ch + (size_t)(row0 + 8) * 768 + ck) =
                        __floats2half2_rn(acc[im][in][2] + b0, acc[im][in][3] + b1);
            }
        }
    } else {
#pragma unroll
        for (int in = 0; in < 4; in++) {
            int col = bn + wn * 32 + in * 8 + 2 * tg;
            float b0 = __ldg(bias + col), b1 = __ldg(bias + col + 1);
#pragma unroll
            for (int im = 0; im < 4; im++) {
                int row0 = bm + wm * 64 + im * 16 + g;
                if (row0 < M)
                    *(float2*)(Cf + (size_t)row0 * CDIM + col) =
                        make_float2(acc[im][in][0] + b0, acc[im][in][1] + b1);
                if (row0 + 8 < M)
                    *(float2*)(Cf + (size_t)(row0 + 8) * CDIM + col) =
                        make_float2(acc[im][in][2] + b0, acc[im][in][3] + b1);
            }
        }
    }
}

// ================= attention: 4 edges/warp, front-batched gathers ==================
// Phase A: all meta shuffles. Phase B: all 8 LDG.128 (k+v, 4 edges) issued
// back-to-back (MLP=8). Phase C: per-edge math consumes landed loads.
__global__ __launch_bounds__(256, 3)
void attn_kernel(const float* __restrict__ tq,  const float* __restrict__ tk,  const float* __restrict__ tv,
                 const float* __restrict__ tqs, const float* __restrict__ tks, const float* __restrict__ tvs,
                 const int* __restrict__ i1c,   const int* __restrict__ i1s) {
    extern __shared__ uint4 smemu4[];
    int hg = blockIdx.y;
    int branch = (hg >= 3) ? 1 : 0;
    int hl = branch ? hg - 3 : hg;
    int bins = branch ? 48 : 47;
    const float* Tq = branch ? tqs : tq;
    const float* Tk = branch ? tks : tk;
    const float* Tv = branch ? tvs : tv;
    const int* i1   = branch ? i1s : i1c;
    const int* ridx = branch ? g_rs : g_rc;

    int entStride = bins * 8;
    int total = 9 * entStride;
    for (int idx = threadIdx.x; idx < total; idx += blockDim.x) {
        int l8 = idx & 7;
        int rest = idx >> 3;
        int bin = rest % bins; rest /= bins;
        int dim = rest % 3;
        int t = rest / 3;
        const float* src = (t == 0) ? Tq : ((t == 1) ? Tk : Tv);
        const float* sp = src + ((bin * 3 + dim) * 3 + hl) * 64 + l8 * 8;
        float4 f0 = ((const float4*)sp)[0];
        float4 f1 = ((const float4*)sp)[1];
        __half2 a = __floats2half2_rn(f0.x, f0.y);
        __half2 b = __floats2half2_rn(f0.z, f0.w);
        __half2 c = __floats2half2_rn(f1.x, f1.y);
        __half2 d = __floats2half2_rn(f1.z, f1.w);
        uint4 u;
        u.x = *(uint32_t*)&a; u.y = *(uint32_t*)&b;
        u.z = *(uint32_t*)&c; u.w = *(uint32_t*)&d;
        smemu4[(t * 3 + dim) * entStride + bin * 8 + l8] = u;
    }
    __syncthreads();

    int lane = threadIdx.x & 31;
    int warp = threadIdx.x >> 5;
    int l8 = lane & 7;
    int g8 = lane >> 3;                 // edge group 0..3
    int qoff = hg * 64;

    const uint4* sq0 = smemu4 + 0 * entStride;
    const uint4* sq1 = smemu4 + 1 * entStride;
    const uint4* sq2 = smemu4 + 2 * entStride;
    const uint4* sk0 = smemu4 + 3 * entStride;
    const uint4* sk1 = smemu4 + 4 * entStride;
    const uint4* sk2 = smemu4 + 5 * entStride;
    const uint4* sv0 = smemu4 + 6 * entStride;
    const uint4* sv1 = smemu4 + 7 * entStride;
    const uint4* sv2 = smemu4 + 8 * entStride;

    const __half* kvh = (const __half*)g_kvh2;

    auto tabsum4 = [&](const uint4* t0, const uint4* t1, const uint4* t2,
                       int r0, int r1, int r2) -> uint4 {
        uint4 a = t0[r0 * 8 + l8];
        uint4 b = t1[r1 * 8 + l8];
        uint4 c = t2[r2 * 8 + l8];
        __half2 s0 = __hadd2(__hadd2(*(__half2*)&a.x, *(__half2*)&b.x), *(__half2*)&c.x);
        __half2 s1 = __hadd2(__hadd2(*(__half2*)&a.y, *(__half2*)&b.y), *(__half2*)&c.y);
        __half2 s2 = __hadd2(__hadd2(*(__half2*)&a.z, *(__half2*)&b.z), *(__half2*)&c.z);
        __half2 s3 = __hadd2(__hadd2(*(__half2*)&a.w, *(__half2*)&b.w), *(__half2*)&c.w);
        uint4 r;
        r.x = *(uint32_t*)&s0; r.y = *(uint32_t*)&s1;
        r.z = *(uint32_t*)&s2; r.w = *(uint32_t*)&s3;
        return r;
    };

    int nstart = blockIdx.x * ATTN_NPB;
    int nend = min(nstart + ATTN_NPB, NPTS);
    for (int n = nstart + warp; n < nend; n += 8) {
        const float* qp = g_q + (size_t)n * CDIM + qoff + l8 * 8;
        float4 qa = ((const float4*)qp)[0];
        float4 qb = ((const float4*)qp)[1];
        qa.x *= SCALE; qa.y *= SCALE; qa.z *= SCALE; qa.w *= SCALE;
        qb.x *= SCALE; qb.y *= SCALE; qb.z *= SCALE; qb.w *= SCALE;

        int ebase = n * KNBR;
        int meta = (lane < 16) ? __ldg(i1 + ebase + lane)
                               : __ldg(ridx + ebase + (lane - 16));

        // ---- phase A: broadcast all edge metadata ----
        int prs[4];
        const __half* jp[4];
#pragma unroll
        for (int t = 0; t < 4; t++) {
            int esrc = 4 * t + g8;
            int j  = __shfl_sync(0xffffffffu, meta, esrc);
            prs[t] = __shfl_sync(0xffffffffu, meta, 16 + esrc);
            jp[t] = kvh + (size_t)j * 768 + qoff + l8 * 8;
        }
        // ---- phase B: front-batch all 8 gathers (MLP=8) ----
        uint4 ku[4], vu[4];
#pragma unroll
        for (int t = 0; t < 4; t++) {
            ku[t] = *(const uint4*)(jp[t]);
            vu[t] = *(const uint4*)(jp[t] + 384);
        }

        // ---- phase C: per-edge math ----
        float s = 0.0f;
        float4 accA = make_float4(0.f, 0.f, 0.f, 0.f);
        float4 accB = make_float4(0.f, 0.f, 0.f, 0.f);
#pragma unroll
        for (int t = 0; t < 4; t++) {
            int pr = prs[t];
            int r0 = pr & 255, r1 = (pr >> 8) & 255, r2 = (pr >> 16) & 255;
            uint4 tqh = tabsum4(sq0, sq1, sq2, r0, r1, r2);
            uint4 tkh = tabsum4(sk0, sk1, sk2, r0, r1, r2);
            float2 k0 = __half22float2(*(__half2*)&ku[t].x);
            float2 k1 = __half22float2(*(__half2*)&ku[t].y);
            float2 k2 = __half22float2(*(__half2*)&ku[t].z);
            float2 k3 = __half22float2(*(__half2*)&ku[t].w);
            float2 tq0 = __half22float2(*(__half2*)&tqh.x);
            float2 tq1 = __half22float2(*(__half2*)&tqh.y);
            float2 tq2 = __half22float2(*(__half2*)&tqh.z);
            float2 tq3 = __half22float2(*(__half2*)&tqh.w);
            float2 tk0 = __half22float2(*(__half2*)&tkh.x);
            float2 tk1 = __half22float2(*(__half2*)&tkh.y);
            float2 tk2 = __half22float2(*(__half2*)&tkh.z);
            float2 tk3 = __half22float2(*(__half2*)&tkh.w);
            float pp = qa.x * (k0.x + tq0.x) + k0.x * tk0.x;
            pp += qa.y * (k0.y + tq0.y) + k0.y * tk0.y;
            pp += qa.z * (k1.x + tq1.x) + k1.x * tk1.x;
            pp += qa.w * (k1.y + tq1.y) + k1.y * tk1.y;
            pp += qb.x * (k2.x + tq2.x) + k2.x * tk2.x;
            pp += qb.y * (k2.y + tq2.y) + k2.y * tk2.y;
            pp += qb.z * (k3.x + tq3.x) + k3.x * tk3.x;
            pp += qb.w * (k3.y + tq3.y) + k3.y * tk3.y;
            pp += __shfl_xor_sync(0xffffffffu, pp, 4);
            pp += __shfl_xor_sync(0xffffffffu, pp, 2);
            pp += __shfl_xor_sync(0xffffffffu, pp, 1);
            float w = __expf(pp);            // scores O(1): no max-shift needed
            s += w;
            uint4 tvh = tabsum4(sv0, sv1, sv2, r0, r1, r2);
            __half2 v0 = __hadd2(*(__half2*)&vu[t].x, *(__half2*)&tvh.x);
            __half2 v1 = __hadd2(*(__half2*)&vu[t].y, *(__half2*)&tvh.y);
            __half2 v2 = __hadd2(*(__half2*)&vu[t].z, *(__half2*)&tvh.z);
            __half2 v3 = __hadd2(*(__half2*)&vu[t].w, *(__half2*)&tvh.w);
            float2 f0 = __half22float2(v0);
            float2 f1 = __half22float2(v1);
            float2 f2 = __half22float2(v2);
            float2 f3 = __half22float2(v3);
            accA.x += w * f0.x; accA.y += w * f0.y;
            accA.z += w * f1.x; accA.w += w * f1.y;
            accB.x += w * f2.x; accB.y += w * f2.y;
            accB.z += w * f3.x; accB.w += w * f3.y;
        }
        // merge the 4 edge groups (xor 8, then xor 16)
#pragma unroll
        for (int d = 8; d <= 16; d <<= 1) {
            s      += __shfl_xor_sync(0xffffffffu, s, d);
            accA.x += __shfl_xor_sync(0xffffffffu, accA.x, d);
            accA.y += __shfl_xor_sync(0xffffffffu, accA.y, d);
            accA.z += __shfl_xor_sync(0xffffffffu, accA.z, d);
            accA.w += __shfl_xor_sync(0xffffffffu, accA.w, d);
            accB.x += __shfl_xor_sync(0xffffffffu, accB.x, d);
            accB.y += __shfl_xor_sync(0xffffffffu, accB.y, d);
            accB.z += __shfl_xor_sync(0xffffffffu, accB.z, d);
            accB.w += __shfl_xor_sync(0xffffffffu, accB.w, d);
        }

        if (lane < 8) {
            float inv = 1.0f / s;
            float o[8] = {accA.x * inv, accA.y * inv, accA.z * inv, accA.w * inv,
                          accB.x * inv, accB.y * inv, accB.z * inv, accB.w * inv};
            __nv_bfloat16 h[8], lo[8];
#pragma unroll
            for (int d = 0; d < 8; d++) {
                h[d]  = __float2bfloat16(o[d]);
                lo[d] = __float2bfloat16(o[d] - __bfloat162float(h[d]));
            }
            uint4 hu, lu;
            __nv_bfloat162 t2;
            t2.x = h[0]; t2.y = h[1]; hu.x = *(uint32_t*)&t2;
            t2.x = h[2]; t2.y = h[3]; hu.y = *(uint32_t*)&t2;
            t2.x = h[4]; t2.y = h[5]; hu.z = *(uint32_t*)&t2;
            t2.x = h[6]; t2.y = h[7]; hu.w = *(uint32_t*)&t2;
            t2.x = lo[0]; t2.y = lo[1]; lu.x = *(uint32_t*)&t2;
            t2.x = lo[2]; t2.y = lo[3]; lu.y = *(uint32_t*)&t2;
            t2.x = lo[4]; t2.y = lo[5]; lu.z = *(uint32_t*)&t2;
            t2.x = lo[6]; t2.y = lo[7]; lu.w = *(uint32_t*)&t2;
            size_t b8 = ((size_t)n * CDIM + qoff) / 8 + l8;
            g_xhi4[b8] = hu;
            g_xlo4[b8] = lu;
        }
    }
}

// ================= launch =================
extern "C" void kernel_launch(void* const* d_in, const int* in_sizes, int n_in,
                              void* d_out, int out_size) {
    const float* qf    = (const float*)d_in[0];
    const float* xyz   = (const float*)d_in[1];
    const int*   i0c   = (const int*)d_in[2];
    const int*   i1c   = (const int*)d_in[3];
    const int*   i0s   = (const int*)d_in[4];
    const int*   i1s   = (const int*)d_in[5];
    const float* Wqkv  = (const float*)d_in[6];
    const float* bqkv  = (const float*)d_in[7];
    const float* Wproj = (const float*)d_in[8];
    const float* bproj = (const float*)d_in[9];
    const float* tq    = (const float*)d_in[10];
    const float* tk    = (const float*)d_in[11];
    const float* tv    = (const float*)d_in[12];
    const float* tqs   = (const float*)d_in[13];
    const float* tks   = (const float*)d_in[14];
    const float* tvs   = (const float*)d_in[15];
    float* out = (float*)d_out;

    float* qbuf;
    __half* kvh;
    __nv_bfloat16 *xhi, *xlo, *wqh, *wql, *wph, *wpl;
    uint2 *ahi2, *alo2;
    cudaGetSymbolAddress((void**)&qbuf, g_q);
    cudaGetSymbolAddress((void**)&kvh, g_kvh2);
    cudaGetSymbolAddress((void**)&ahi2, g_ahi4);
    cudaGetSymbolAddress((void**)&alo2, g_alo4);
    cudaGetSymbolAddress((void**)&xhi, g_xhi4);
    cudaGetSymbolAddress((void**)&xlo, g_xlo4);
    cudaGetSymbolAddress((void**)&wqh, g_wqh4);
    cudaGetSymbolAddress((void**)&wql, g_wql4);
    cudaGetSymbolAddress((void**)&wph, g_wph4);
    cudaGetSymbolAddress((void**)&wpl, g_wpl4);

    int mtiles = MPAD / 128;       // 157
    int gemm_smem = NSTAGE * BUFB; // 98304
    cudaFuncSetAttribute(gemm_mma, cudaFuncAttributeMaxDynamicSharedMemorySize, gemm_smem);

    // split conversions + prep
    conv_split_kernel<<<(MPAD * CDIM / 4 + 255) / 256, 256>>>(qf, ahi2, alo2, NPTS, MPAD);
    conv_wt_kernel<<<dim3(QKVW / 32, CDIM / 32), dim3(32, 8)>>>(Wqkv, wqh, wql, QKVW);
    conv_wt_kernel<<<dim3(CDIM / 32, CDIM / 32), dim3(32, 8)>>>(Wproj, wph, wpl, CDIM);
    sphere_kernel<<<(NPTS + 255) / 256, 256>>>(xyz);
    prep_kernel<<<(MEDG + 255) / 256, 256>>>(xyz, i0c, i1c, i0s, i1s);

    // QKV projection: q -> fp32 g_q, k/v -> fp16 g_kvh
    gemm_mma<<<dim3(QKVW / 128, mtiles), 256, gemm_smem>>>(
        (const __nv_bfloat16*)ahi2, (const __nv_bfloat16*)alo2, wqh, wql, bqkv,
        qbuf, kvh, NPTS);

    // attention (front-batched gathers; 3 CTA/SM single wave)
    int attn_smem = 9 * 48 * 8 * sizeof(uint4);  // 55296
    cudaFuncSetAttribute(attn_kernel, cudaFuncAttributeMaxDynamicSharedMemorySize, attn_smem);
    attn_kernel<<<dim3(ATTN_BX, HEADS), 256, attn_smem>>>(tq, tk, tv, tqs, tks, tvs, i1c, i1s);

    // output projection (pure fp32 path)
    gemm_mma<<<dim3(CDIM / 128, mtiles), 256, gemm_smem>>>(
        xhi, xlo, wph, wpl, bproj, out, (__half*)nullptr, NPTS);
}